// round 1
// baseline (speedup 1.0000x reference)
#include <cuda_runtime.h>
#include <cstddef>

// Problem constants (fixed by the dataset):
//   B=2, N=4096, K=48, Q=20
//   inputs : d_in[0]=S (int32, B*N), d_in[1]=h (f32, B*N*Q),
//            d_in[2]=J (f32, B*N*K*Q*Q), d_in[3]=edge_idx (int32, B*N*K)
//   output : d_out = [ U (B) | U_i (B*N*Q) ]  (fp32, 163842 elems)

namespace {
constexpr int Bc = 2;
constexpr int Nc = 4096;
constexpr int Kc = 48;
constexpr int Qc = 20;
constexpr int WARPS_PER_BLOCK = 8;
}

// Kernel 1: compute U_i[b,i,q] = h[b,i,q] + sum_k J[b,i,k,q,S[edge_idx[b,i,k]]]
// One warp per (b,i). Lanes cooperatively gather the 48 neighbor states into
// shared memory, then lanes 0..19 each own one q and fully unroll over k
// (48 independent LDGs in flight -> deep MLP, hides DRAM + TLB latency).
__global__ __launch_bounds__(WARPS_PER_BLOCK * 32)
void potts_ui_kernel(const int* __restrict__ S,
                     const float* __restrict__ h,
                     const float* __restrict__ J,
                     const int* __restrict__ eidx,
                     float* __restrict__ out)
{
    const int w     = threadIdx.x >> 5;
    const int lane  = threadIdx.x & 31;
    const int group = blockIdx.x * WARPS_PER_BLOCK + w;   // group = b*N + i
    const int b     = group >> 12;                         // /N (N=4096)

    __shared__ int s_sh[WARPS_PER_BLOCK][Kc];

    // Coalesced load of 48 edge indices, then gather neighbor states.
    // S is tiny (32 KB total) -> L1/L2 resident after first wave.
    const int* e  = eidx + (size_t)group * Kc;
    const int* Sb = S + b * Nc;
    for (int k = lane; k < Kc; k += 32) {
        s_sh[w][k] = Sb[e[k]];
    }
    __syncwarp();

    if (lane < Qc) {
        // Row pointer for this q: J[group][k][lane][*], stride Qc*Qc per k.
        const float* Jg = J + (size_t)group * (Kc * Qc * Qc) + (size_t)lane * Qc;

        float a0 = 0.f, a1 = 0.f, a2 = 0.f, a3 = 0.f;
        #pragma unroll
        for (int k = 0; k < Kc; k += 4) {
            a0 += __ldg(Jg + (size_t)(k + 0) * (Qc * Qc) + s_sh[w][k + 0]);
            a1 += __ldg(Jg + (size_t)(k + 1) * (Qc * Qc) + s_sh[w][k + 1]);
            a2 += __ldg(Jg + (size_t)(k + 2) * (Qc * Qc) + s_sh[w][k + 2]);
            a3 += __ldg(Jg + (size_t)(k + 3) * (Qc * Qc) + s_sh[w][k + 3]);
        }
        const float ji = (a0 + a1) + (a2 + a3);
        const float ui = h[(size_t)group * Qc + lane] + ji;
        out[Bc + (size_t)group * Qc + lane] = ui;
    }
}

// Kernel 2: U[b] = sum_i ( h[b,i,s] + 0.5*J_i[b,i,s] )
//                = sum_i 0.5 * ( U_i[b,i,s] + h[b,i,s] ),  s = S[b,i]
// Deterministic tree reduction (no float atomics). One block per batch.
__global__ __launch_bounds__(256)
void potts_u_kernel(const int* __restrict__ S,
                    const float* __restrict__ h,
                    float* __restrict__ out)
{
    const int b = blockIdx.x;
    __shared__ float red[256];

    float sum = 0.f;
    for (int i = threadIdx.x; i < Nc; i += 256) {
        const int    gi = b * Nc + i;
        const int    s  = S[gi];
        const float  ui = out[Bc + (size_t)gi * Qc + s];
        const float  hv = h[(size_t)gi * Qc + s];
        sum += 0.5f * (ui + hv);
    }
    red[threadIdx.x] = sum;
    __syncthreads();
    #pragma unroll
    for (int st = 128; st > 0; st >>= 1) {
        if (threadIdx.x < st) red[threadIdx.x] += red[threadIdx.x + st];
        __syncthreads();
    }
    if (threadIdx.x == 0) out[b] = red[0];
}

extern "C" void kernel_launch(void* const* d_in, const int* in_sizes, int n_in,
                              void* d_out, int out_size)
{
    const int*   S    = (const int*)  d_in[0];
    const float* h    = (const float*)d_in[1];
    const float* J    = (const float*)d_in[2];
    const int*   eidx = (const int*)  d_in[3];
    float*       out  = (float*)      d_out;

    const int groups = Bc * Nc;                       // 8192
    const int blocks = groups / WARPS_PER_BLOCK;      // 1024

    potts_ui_kernel<<<blocks, WARPS_PER_BLOCK * 32>>>(S, h, J, eidx, out);
    potts_u_kernel<<<Bc, 256>>>(S, h, out);

    (void)in_sizes; (void)n_in; (void)out_size;
}

// round 2
// speedup vs baseline: 1.1152x; 1.1152x over previous
#include <cuda_runtime.h>
#include <cstddef>

// Problem constants (fixed by the dataset):
//   B=2, N=4096, K=48, Q=20
//   inputs : d_in[0]=S (int32, B*N), d_in[1]=h (f32, B*N*Q),
//            d_in[2]=J (f32, B*N*K*Q*Q), d_in[3]=edge_idx (int32, B*N*K)
//   output : d_out = [ U (B) | U_i (B*N*Q) ]  (fp32, 163842 elems)

namespace {
constexpr int Bc = 2;
constexpr int Nc = 4096;
constexpr int Kc = 48;
constexpr int Qc = 20;
constexpr int GPB = 16;                 // groups per block
constexpr int TPB = GPB * Qc;           // 320 threads per block
constexpr int GROUPS = Bc * Nc;         // 8192
}

// Per-group contribution to U: 0.5*(U_i[g,s] + h[g,s]), s = S[g].
__device__ float g_contrib[GROUPS];

// Kernel 1: U_i[g,q] = h[g,q] + sum_k J[g,k,q,S[edge_idx[g,k]]]
// Dense mapping: thread = (group, q). All 32 lanes of every warp issue LDGs;
// U_i stores are fully contiguous across the block. Each thread keeps 48
// independent loads in flight (deep MLP hides DRAM + TLB latency).
__global__ __launch_bounds__(TPB)
void potts_ui_kernel(const int* __restrict__ S,
                     const float* __restrict__ h,
                     const float* __restrict__ J,
                     const int* __restrict__ eidx,
                     float* __restrict__ out)
{
    const int tid   = threadIdx.x;
    const int gl    = tid / Qc;                 // 0..15 group-in-block
    const int q     = tid - gl * Qc;            // 0..19
    const int group = blockIdx.x * GPB + gl;    // 0..8191

    __shared__ int s_sh[GPB][Kc];

    // Cooperative load of this block's 16*48 edge indices + gather of
    // neighbor states (S is 32 KB total -> L2 resident).
    const int ebase = blockIdx.x * GPB * Kc;
    #pragma unroll
    for (int t = tid; t < GPB * Kc; t += TPB) {
        const int g_of = t / Kc;
        const int k_of = t - g_of * Kc;
        const int grp  = blockIdx.x * GPB + g_of;
        const int b_of = grp >> 12;             // grp / N
        s_sh[g_of][k_of] = S[b_of * Nc + eidx[ebase + t]];
    }
    __syncthreads();

    // Row pointer for this q: J[group][k][q][*], stride Q*Q floats per k.
    const float* Jg   = J + (size_t)group * (Kc * Qc * Qc) + (size_t)q * Qc;
    const int*   srow = s_sh[gl];

    float a0 = 0.f, a1 = 0.f, a2 = 0.f, a3 = 0.f;
    #pragma unroll
    for (int k = 0; k < Kc; k += 4) {
        a0 += __ldg(Jg + (size_t)(k + 0) * (Qc * Qc) + srow[k + 0]);
        a1 += __ldg(Jg + (size_t)(k + 1) * (Qc * Qc) + srow[k + 1]);
        a2 += __ldg(Jg + (size_t)(k + 2) * (Qc * Qc) + srow[k + 2]);
        a3 += __ldg(Jg + (size_t)(k + 3) * (Qc * Qc) + srow[k + 3]);
    }
    const float ji = (a0 + a1) + (a2 + a3);
    const float hv = h[(size_t)group * Qc + q];
    const float ui = hv + ji;
    out[Bc + (size_t)group * Qc + q] = ui;

    // U contribution: only the thread whose q equals this group's own state.
    // U_term = h[s] + 0.5*J_i[s] = 0.5*(U_i[s] + h[s])
    if (q == S[group]) {
        g_contrib[group] = 0.5f * (ui + hv);
    }
}

// Kernel 2: U[b] = deterministic tree-sum of 4096 per-group contributions.
__global__ __launch_bounds__(256)
void potts_u_kernel(float* __restrict__ out)
{
    const int b = blockIdx.x;
    __shared__ float red[256];

    const float* c = g_contrib + b * Nc;
    float sum = 0.f;
    #pragma unroll
    for (int j = 0; j < Nc / 256; j++) {
        sum += c[threadIdx.x + 256 * j];
    }
    red[threadIdx.x] = sum;
    __syncthreads();
    #pragma unroll
    for (int st = 128; st > 0; st >>= 1) {
        if (threadIdx.x < st) red[threadIdx.x] += red[threadIdx.x + st];
        __syncthreads();
    }
    if (threadIdx.x == 0) out[b] = red[0];
}

extern "C" void kernel_launch(void* const* d_in, const int* in_sizes, int n_in,
                              void* d_out, int out_size)
{
    const int*   S    = (const int*)  d_in[0];
    const float* h    = (const float*)d_in[1];
    const float* J    = (const float*)d_in[2];
    const int*   eidx = (const int*)  d_in[3];
    float*       out  = (float*)      d_out;

    const int blocks = GROUPS / GPB;   // 512

    potts_ui_kernel<<<blocks, TPB>>>(S, h, J, eidx, out);
    potts_u_kernel<<<Bc, 256>>>(out);

    (void)in_sizes; (void)n_in; (void)out_size;
}

// round 3
// speedup vs baseline: 1.1646x; 1.0443x over previous
#include <cuda_runtime.h>
#include <cstddef>

// B=2, N=4096, K=48, Q=20
// inputs : d_in[0]=S (i32, B*N), d_in[1]=h (f32, B*N*Q),
//          d_in[2]=J (f32, B*N*K*Q*Q), d_in[3]=edge_idx (i32, B*N*K)
// output : d_out = [ U (B) | U_i (B*N*Q) ] fp32

namespace {
constexpr int Bc = 2;
constexpr int Nc = 4096;
constexpr int Kc = 48;
constexpr int Qc = 20;
constexpr int GPB = 16;                 // groups per block
constexpr int TPB = GPB * Qc;           // 320 threads
constexpr int GROUPS = Bc * Nc;         // 8192
constexpr int NBLK = GROUPS / GPB;      // 512
}

// Per-block partial sums of U contributions (256 blocks per batch).
__device__ float g_partial[NBLK];

// Kernel 1: U_i[g,q] = h[g,q] + sum_k J[g,k,q,S[edge_idx[g,k]]]
// thread = (group, q); per-block reduction of U contributions.
__global__ __launch_bounds__(TPB)
void potts_ui_kernel(const int* __restrict__ S,
                     const float* __restrict__ h,
                     const float* __restrict__ J,
                     const int* __restrict__ eidx,
                     float* __restrict__ out)
{
    const int tid   = threadIdx.x;
    const int gl    = tid / Qc;                 // 0..15
    const int q     = tid - gl * Qc;            // 0..19
    const int group = blockIdx.x * GPB + gl;

    __shared__ int   s_sh[GPB][Kc];
    __shared__ float c_sh[GPB];

    // Gather this block's 16*48 neighbor states (S: 32 KB, L2-resident).
    const int ebase = blockIdx.x * GPB * Kc;
    #pragma unroll
    for (int t = tid; t < GPB * Kc; t += TPB) {
        const int g_of = t / Kc;
        const int k_of = t - g_of * Kc;
        const int grp  = blockIdx.x * GPB + g_of;
        const int b_of = grp >> 12;
        s_sh[g_of][k_of] = S[b_of * Nc + eidx[ebase + t]];
    }
    __syncthreads();

    const float* Jg   = J + (size_t)group * (Kc * Qc * Qc) + (size_t)q * Qc;
    const int*   srow = s_sh[gl];

    float a0 = 0.f, a1 = 0.f, a2 = 0.f, a3 = 0.f;
    #pragma unroll
    for (int k = 0; k < Kc; k += 4) {
        a0 += __ldcs(Jg + (size_t)(k + 0) * (Qc * Qc) + srow[k + 0]);
        a1 += __ldcs(Jg + (size_t)(k + 1) * (Qc * Qc) + srow[k + 1]);
        a2 += __ldcs(Jg + (size_t)(k + 2) * (Qc * Qc) + srow[k + 2]);
        a3 += __ldcs(Jg + (size_t)(k + 3) * (Qc * Qc) + srow[k + 3]);
    }
    const float ji = (a0 + a1) + (a2 + a3);
    const float hv = h[(size_t)group * Qc + q];
    const float ui = hv + ji;
    out[Bc + (size_t)group * Qc + q] = ui;

    // U contribution for this group: 0.5*(U_i[s] + h[s]), s = S[group].
    if (q == S[group]) {
        c_sh[gl] = 0.5f * (ui + hv);
    }
    __syncthreads();
    if (tid == 0) {
        float s = 0.f;
        #pragma unroll
        for (int g = 0; g < GPB; g++) s += c_sh[g];
        g_partial[blockIdx.x] = s;
    }
}

// Kernel 2: fold 256 per-block partials per batch.
__global__ __launch_bounds__(256)
void potts_u_final(float* __restrict__ out)
{
    const int b = blockIdx.x;
    __shared__ float red[256];
    red[threadIdx.x] = g_partial[b * (NBLK / Bc) + threadIdx.x];
    __syncthreads();
    #pragma unroll
    for (int st = 128; st > 0; st >>= 1) {
        if (threadIdx.x < st) red[threadIdx.x] += red[threadIdx.x + st];
        __syncthreads();
    }
    if (threadIdx.x == 0) out[b] = red[0];
}

// Empty kernel: shifts ncu's launch index (-s 5) so the capture lands on
// potts_ui_kernel instead of the tiny reducer. Removed once profiled.
__global__ void potts_nop() {}

extern "C" void kernel_launch(void* const* d_in, const int* in_sizes, int n_in,
                              void* d_out, int out_size)
{
    const int*   S    = (const int*)  d_in[0];
    const float* h    = (const float*)d_in[1];
    const float* J    = (const float*)d_in[2];
    const int*   eidx = (const int*)  d_in[3];
    float*       out  = (float*)      d_out;

    // Launch order: nop, ui, nop, final  ->  global launch index 5 = ui.
    potts_nop<<<1, 32>>>();
    potts_ui_kernel<<<NBLK, TPB>>>(S, h, J, eidx, out);
    potts_nop<<<1, 32>>>();
    potts_u_final<<<Bc, 256>>>(out);

    (void)in_sizes; (void)n_in; (void)out_size;
}

// round 4
// speedup vs baseline: 1.1905x; 1.0223x over previous
#include <cuda_runtime.h>
#include <cstddef>

// B=2, N=4096, K=48, Q=20
// inputs : d_in[0]=S (i32, B*N), d_in[1]=h (f32, B*N*Q),
//          d_in[2]=J (f32, B*N*K*Q*Q), d_in[3]=edge_idx (i32, B*N*K)
// output : d_out = [ U (B) | U_i (B*N*Q) ] fp32

namespace {
constexpr int Bc = 2;
constexpr int Nc = 4096;
constexpr int Kc = 48;
constexpr int Qc = 20;
constexpr int GPB = 16;                 // groups per block
constexpr int TPB = GPB * Qc;           // 320 threads
constexpr int GROUPS = Bc * Nc;         // 8192
constexpr int NBLK = GROUPS / GPB;      // 512  (256 per batch)
constexpr int BLK_PER_B = NBLK / Bc;    // 256
}

__device__ float g_partial[NBLK];
__device__ int   g_count = 0;           // self-resetting epoch counter

// Fused kernel:
//   U_i[g,q] = h[g,q] + sum_k J[g,k,q, S[edge_idx[g,k]]]
//   U[b]     = sum_g 0.5*(U_i[g,s]+h[g,s]), s=S[g]   (last-block reduction)
__global__ __launch_bounds__(TPB)
void potts_fused_kernel(const int* __restrict__ S,
                        const float* __restrict__ h,
                        const float* __restrict__ J,
                        const int* __restrict__ eidx,
                        float* __restrict__ out)
{
    const int tid   = threadIdx.x;
    const int gl    = tid / Qc;                 // 0..15
    const int q     = tid - gl * Qc;            // 0..19
    const int group = blockIdx.x * GPB + gl;

    __shared__ int   s_sh[GPB][Kc];
    __shared__ float c_sh[GPB];
    __shared__ float red[BLK_PER_B];
    __shared__ bool  is_last;

    // Gather this block's 16*48 neighbor states (S: 32 KB, L2-resident).
    const int ebase = blockIdx.x * GPB * Kc;
    #pragma unroll
    for (int t = tid; t < GPB * Kc; t += TPB) {
        const int g_of = t / Kc;
        const int k_of = t - g_of * Kc;
        const int grp  = blockIdx.x * GPB + g_of;
        const int b_of = grp >> 12;
        s_sh[g_of][k_of] = S[b_of * Nc + eidx[ebase + t]];
    }
    __syncthreads();

    const float* Jg   = J + (size_t)group * (Kc * Qc * Qc) + (size_t)q * Qc;
    const int*   srow = s_sh[gl];

    float a0 = 0.f, a1 = 0.f, a2 = 0.f, a3 = 0.f;
    #pragma unroll
    for (int k = 0; k < Kc; k += 4) {
        a0 += __ldcs(Jg + (size_t)(k + 0) * (Qc * Qc) + srow[k + 0]);
        a1 += __ldcs(Jg + (size_t)(k + 1) * (Qc * Qc) + srow[k + 1]);
        a2 += __ldcs(Jg + (size_t)(k + 2) * (Qc * Qc) + srow[k + 2]);
        a3 += __ldcs(Jg + (size_t)(k + 3) * (Qc * Qc) + srow[k + 3]);
    }
    const float ji = (a0 + a1) + (a2 + a3);
    const float hv = h[(size_t)group * Qc + q];
    const float ui = hv + ji;
    out[Bc + (size_t)group * Qc + q] = ui;

    // Per-group U contribution: 0.5*(U_i[s]+h[s]) at s = S[group].
    if (q == S[group]) {
        c_sh[gl] = 0.5f * (ui + hv);
    }
    __syncthreads();

    // Per-block partial + epoch counter (threadFenceReduction pattern).
    if (tid == 0) {
        float s = 0.f;
        #pragma unroll
        for (int g = 0; g < GPB; g++) s += c_sh[g];
        g_partial[blockIdx.x] = s;
        __threadfence();
        const int prev = atomicAdd(&g_count, 1);
        is_last = (prev == NBLK - 1);
    }
    __syncthreads();

    if (is_last) {
        // Deterministic tree reduction of the 256 partials per batch.
        #pragma unroll
        for (int b = 0; b < Bc; b++) {
            if (tid < BLK_PER_B) red[tid] = g_partial[b * BLK_PER_B + tid];
            __syncthreads();
            #pragma unroll
            for (int st = BLK_PER_B / 2; st > 0; st >>= 1) {
                if (tid < st) red[tid] += red[tid + st];
                __syncthreads();
            }
            if (tid == 0) out[b] = red[0];
            __syncthreads();
        }
        if (tid == 0) g_count = 0;   // reset for next graph replay
    }
}

extern "C" void kernel_launch(void* const* d_in, const int* in_sizes, int n_in,
                              void* d_out, int out_size)
{
    const int*   S    = (const int*)  d_in[0];
    const float* h    = (const float*)d_in[1];
    const float* J    = (const float*)d_in[2];
    const int*   eidx = (const int*)  d_in[3];
    float*       out  = (float*)      d_out;

    potts_fused_kernel<<<NBLK, TPB>>>(S, h, J, eidx, out);

    (void)in_sizes; (void)n_in; (void)out_size;
}